// round 8
// baseline (speedup 1.0000x reference)
#include <cuda_runtime.h>
#include <cuda_bf16.h>
#include <math.h>
#include <stdint.h>

// ---------------------------------------------------------------------------
// Problem constants
// ---------------------------------------------------------------------------
#define NB   4        // batch
#define NT   1024     // time steps
#define NL   512      // latent / emb
#define NV   50257    // vocab
#define NR   (NB*NT)  // 4096 rows
#define NVP  50304    // padded vocab pitch (= 393*128, 16B-aligned rows)

// small GEMM tiling (register-staged)
#define BM   256
#define BN   128
#define BK   16
#define GT   512
#define GEMM_SMEM ((2*BM*20 + 2*BK*136)*4)

// big GEMM tiling (cp.async pipelined)
#define UBM 128
#define UBN 128
#define UBK 16
#define UST 4
#define UAS (UBM*20)
#define UBS (UBK*132)
#define UGEMM_SMEM (UST*(UAS+UBS)*4)

// ---------------------------------------------------------------------------
// Scratch (device globals — no allocation allowed)
// ---------------------------------------------------------------------------
__device__ float g_bufA[NR * NL];     // XW0 (= embed[x]@Wx0 + b0)
__device__ float g_bufB[NR * NL];     // H1, stored tf32-rounded
__device__ float g_wu[NL * NVP];      // Wu, tf32-rounded + padded
__device__ float4 g_h0[2][NL];        // depth-2 ring, layer-0 h, [k]={b0..b3}
__device__ float4 g_h1[2][NL];        // depth-2 ring, layer-1 h
__device__ unsigned g_bar;            // single joint barrier counter

// ---------------------------------------------------------------------------
// Helpers
// ---------------------------------------------------------------------------
__device__ __forceinline__ unsigned f2tf32(float f) {
    unsigned u;
    asm("cvt.rna.tf32.f32 %0, %1;" : "=r"(u) : "f"(f));
    return u;
}

__device__ __forceinline__ void mma_tf32(float c[4], const unsigned a[4],
                                         const unsigned b[2]) {
    asm volatile(
        "mma.sync.aligned.m16n8k8.row.col.f32.tf32.tf32.f32 "
        "{%0,%1,%2,%3},{%4,%5,%6,%7},{%8,%9},{%0,%1,%2,%3};"
        : "+f"(c[0]), "+f"(c[1]), "+f"(c[2]), "+f"(c[3])
        : "r"(a[0]), "r"(a[1]), "r"(a[2]), "r"(a[3]), "r"(b[0]), "r"(b[1]));
}

__device__ __forceinline__ void cp16(uint32_t dst, const void* src) {
    asm volatile("cp.async.cg.shared.global [%0], [%1], 16;\n"
                 :: "r"(dst), "l"(src));
}

// packed f32x2 ops (Blackwell)
__device__ __forceinline__ void ffma2(unsigned long long& d,
                                      unsigned long long a,
                                      unsigned long long b) {
    asm("fma.rn.f32x2 %0, %1, %2, %0;" : "+l"(d) : "l"(a), "l"(b));
}
__device__ __forceinline__ void fadd2(unsigned long long& d,
                                      unsigned long long a) {
    asm("add.rn.f32x2 %0, %0, %1;" : "+l"(d) : "l"(a));
}
__device__ __forceinline__ unsigned long long fpack2(float f) {
    unsigned long long u;
    asm("mov.b64 %0, {%1, %1};" : "=l"(u) : "f"(f));
    return u;
}

// ---------------------------------------------------------------------------
// init: reset barrier + zero both h rings
// ---------------------------------------------------------------------------
__global__ void init_kernel() {
    const int tid = threadIdx.x;
    if (tid == 0) g_bar = 0u;
    float4 z = make_float4(0.f, 0.f, 0.f, 0.f);
    for (int i = tid; i < 2 * NL; i += 256) {
        ((float4*)g_h0)[i] = z;
        ((float4*)g_h1)[i] = z;
    }
}

// ---------------------------------------------------------------------------
// Wu prep: g_wu[k][n] = tf32_rna(Wu[k][n]), zero-padded to pitch NVP
// ---------------------------------------------------------------------------
__global__ void wu_prep(const float* __restrict__ Wu) {
    const int n = blockIdx.x * 256 + threadIdx.x;
    const int k = blockIdx.y;
    if (n < NVP)
        g_wu[(size_t)k * NVP + n] =
            (n < NV) ? __uint_as_float(f2tf32(Wu[(size_t)k * NV + n])) : 0.f;
}

// ---------------------------------------------------------------------------
// Small GEMM: C = A(gathered) @ B + bias (in-loop tf32 cvt). XW0 only.
// ---------------------------------------------------------------------------
__global__ __launch_bounds__(GT, 1)
void gemm_tf32(const float* __restrict__ A, const int* __restrict__ gidx,
               const float* __restrict__ B, const float* __restrict__ bias,
               float* __restrict__ C, int N) {
    extern __shared__ float sm[];
    float* As = sm;
    float* Bs = sm + 2 * BM * 20;

    const int tid  = threadIdx.x;
    const int lane = tid & 31;
    const int warp = tid >> 5;
    const int wm = warp & 3;
    const int wn = warp >> 2;
    const int g  = lane >> 2;
    const int t4 = lane & 3;

    const int rowBase = blockIdx.y * BM;
    const int nb      = blockIdx.x * BN;

    float acc[4][4][4];
#pragma unroll
    for (int a = 0; a < 4; ++a)
#pragma unroll
        for (int b = 0; b < 4; ++b)
#pragma unroll
            for (int e = 0; e < 4; ++e) acc[a][b][e] = 0.f;

    const int rl0 = tid >> 2;
    const int rl1 = rl0 + 128;
    const int c4  = tid & 3;
    const float* arow0;
    const float* arow1;
    {
        const int r0 = rowBase + rl0;
        const int r1 = rowBase + rl1;
        arow0 = A + (size_t)(gidx ? gidx[r0] : r0) * NL;
        arow1 = A + (size_t)(gidx ? gidx[r1] : r1) * NL;
    }

    float4 pa0, pa1;
    float  pb[4];
    pa0 = *(const float4*)(arow0 + c4 * 4);
    pa1 = *(const float4*)(arow1 + c4 * 4);
#pragma unroll
    for (int i = 0; i < 4; ++i) {
        const int id  = tid + i * GT;
        const int kr  = id >> 7;
        const int col = id & 127;
        const int n   = nb + col;
        pb[i] = (n < N) ? B[(size_t)kr * N + n] : 0.f;
    }

    int w = 0;
    for (int kb = 0; kb < NL; kb += BK) {
        {
            float4 w0, w1;
            w0.x = __uint_as_float(f2tf32(pa0.x));
            w0.y = __uint_as_float(f2tf32(pa0.y));
            w0.z = __uint_as_float(f2tf32(pa0.z));
            w0.w = __uint_as_float(f2tf32(pa0.w));
            w1.x = __uint_as_float(f2tf32(pa1.x));
            w1.y = __uint_as_float(f2tf32(pa1.y));
            w1.z = __uint_as_float(f2tf32(pa1.z));
            w1.w = __uint_as_float(f2tf32(pa1.w));
            *(float4*)&As[w * (BM * 20) + rl0 * 20 + c4 * 4] = w0;
            *(float4*)&As[w * (BM * 20) + rl1 * 20 + c4 * 4] = w1;
#pragma unroll
            for (int i = 0; i < 4; ++i) {
                const int id  = tid + i * GT;
                const int kr  = id >> 7;
                const int col = id & 127;
                Bs[w * (BK * 136) + kr * 136 + col] =
                    __uint_as_float(f2tf32(pb[i]));
            }
        }
        __syncthreads();

        if (kb + BK < NL) {
            pa0 = *(const float4*)(arow0 + kb + BK + c4 * 4);
            pa1 = *(const float4*)(arow1 + kb + BK + c4 * 4);
#pragma unroll
            for (int i = 0; i < 4; ++i) {
                const int id  = tid + i * GT;
                const int kr  = id >> 7;
                const int col = id & 127;
                const int n   = nb + col;
                pb[i] = (n < N) ? B[(size_t)(kb + BK + kr) * N + n] : 0.f;
            }
        }

        const float* Aw = &As[w * (BM * 20)];
        const float* Bw = &Bs[w * (BK * 136)];
#pragma unroll
        for (int ks = 0; ks < BK; ks += 8) {
            unsigned af[4][4], bf[4][2];
#pragma unroll
            for (int im = 0; im < 4; ++im) {
                const int m0 = wm * 64 + im * 16;
                const float* a0 = Aw + (m0 + g) * 20 + ks + t4;
                const float* a1 = Aw + (m0 + g + 8) * 20 + ks + t4;
                af[im][0] = __float_as_uint(a0[0]);
                af[im][1] = __float_as_uint(a1[0]);
                af[im][2] = __float_as_uint(a0[4]);
                af[im][3] = __float_as_uint(a1[4]);
            }
#pragma unroll
            for (int in = 0; in < 4; ++in) {
                const int n0 = wn * 32 + in * 8;
                bf[in][0] = __float_as_uint(Bw[(ks + t4) * 136 + n0 + g]);
                bf[in][1] = __float_as_uint(Bw[(ks + t4 + 4) * 136 + n0 + g]);
            }
#pragma unroll
            for (int im = 0; im < 4; ++im)
#pragma unroll
                for (int in = 0; in < 4; ++in)
                    mma_tf32(acc[im][in], af[im], bf[in]);
        }
        w ^= 1;
    }

#pragma unroll
    for (int im = 0; im < 4; ++im) {
        const int r0 = rowBase + wm * 64 + im * 16 + g;
#pragma unroll
        for (int in = 0; in < 4; ++in) {
            const int c0 = nb + wn * 32 + in * 8 + t4 * 2;
#pragma unroll
            for (int e = 0; e < 4; ++e) {
                const int row = r0 + ((e & 2) ? 8 : 0);
                const int col = c0 + (e & 1);
                if (col < N)
                    C[(size_t)row * N + col] = acc[im][in][e] + bias[col];
            }
        }
    }
}

// ---------------------------------------------------------------------------
// Big unembed GEMM: out = H1(tf32 bits) @ g_wu + bu. 128x128x16, cp.async x4.
// ---------------------------------------------------------------------------
__global__ __launch_bounds__(256, 2)
void gemm_unembed(const float* __restrict__ A, const float* __restrict__ bias,
                  float* __restrict__ C) {
    extern __shared__ float sm[];
    const uint32_t smem_u32 = (uint32_t)__cvta_generic_to_shared(sm);

    const int tid  = threadIdx.x;
    const int lane = tid & 31;
    const int warp = tid >> 5;
    const int wm = warp & 1;
    const int wn = warp >> 1;
    const int g  = lane >> 2;
    const int t4 = lane & 3;

    const int rowBase = blockIdx.y * UBM;
    const int nb      = blockIdx.x * UBN;

    float acc[4][4][4];
#pragma unroll
    for (int a = 0; a < 4; ++a)
#pragma unroll
        for (int b = 0; b < 4; ++b)
#pragma unroll
            for (int e = 0; e < 4; ++e) acc[a][b][e] = 0.f;

    const int arow = tid >> 2;
    const int ac4  = tid & 3;
    const float* aptr0 = A + (size_t)(rowBase + arow) * NL + ac4 * 4;
    const float* aptr1 = A + (size_t)(rowBase + arow + 64) * NL + ac4 * 4;
    const int bkr0 = tid >> 5;
    const int bc0  = tid & 31;
    const float* bptr0 = g_wu + (size_t)bkr0 * NVP + nb + bc0 * 4;
    const float* bptr1 = g_wu + (size_t)(bkr0 + 8) * NVP + nb + bc0 * 4;

    const uint32_t adst0 = smem_u32 + (arow * 20 + ac4 * 4) * 4;
    const uint32_t adst1 = smem_u32 + ((arow + 64) * 20 + ac4 * 4) * 4;
    const uint32_t bdst0 = smem_u32 + (UST * UAS + bkr0 * 132 + bc0 * 4) * 4;
    const uint32_t bdst1 = smem_u32 + (UST * UAS + (bkr0 + 8) * 132 + bc0 * 4) * 4;

    const int NKT = NL / UBK;

#pragma unroll
    for (int s = 0; s < UST - 1; ++s) {
        const int kb = s * UBK;
        cp16(adst0 + s * UAS * 4, aptr0 + kb);
        cp16(adst1 + s * UAS * 4, aptr1 + kb);
        cp16(bdst0 + s * UBS * 4, bptr0 + (size_t)kb * NVP);
        cp16(bdst1 + s * UBS * 4, bptr1 + (size_t)kb * NVP);
        asm volatile("cp.async.commit_group;\n" ::);
    }

    for (int kt = 0; kt < NKT; ++kt) {
        asm volatile("cp.async.wait_group 2;\n" ::);
        __syncthreads();

        if (kt + UST - 1 < NKT) {
            const int s  = (kt + UST - 1) & (UST - 1);
            const int kb = (kt + UST - 1) * UBK;
            cp16(adst0 + s * UAS * 4, aptr0 + kb);
            cp16(adst1 + s * UAS * 4, aptr1 + kb);
            cp16(bdst0 + s * UBS * 4, bptr0 + (size_t)kb * NVP);
            cp16(bdst1 + s * UBS * 4, bptr1 + (size_t)kb * NVP);
        }
        asm volatile("cp.async.commit_group;\n" ::);

        const float* Aw = sm + (kt & (UST - 1)) * UAS;
        const float* Bw = sm + UST * UAS + (kt & (UST - 1)) * UBS;
#pragma unroll
        for (int ks = 0; ks < UBK; ks += 8) {
            unsigned af[4][4], bf[4][2];
#pragma unroll
            for (int im = 0; im < 4; ++im) {
                const int m0 = wm * 64 + im * 16;
                const float* a0 = Aw + (m0 + g) * 20 + ks + t4;
                const float* a1 = Aw + (m0 + g + 8) * 20 + ks + t4;
                af[im][0] = __float_as_uint(a0[0]);
                af[im][1] = __float_as_uint(a1[0]);
                af[im][2] = __float_as_uint(a0[4]);
                af[im][3] = __float_as_uint(a1[4]);
            }
#pragma unroll
            for (int in = 0; in < 4; ++in) {
                const int n0 = wn * 32 + in * 8;
                bf[in][0] = __float_as_uint(Bw[(ks + t4) * 132 + n0 + g]);
                bf[in][1] = __float_as_uint(Bw[(ks + t4 + 4) * 132 + n0 + g]);
            }
#pragma unroll
            for (int im = 0; im < 4; ++im)
#pragma unroll
                for (int in = 0; in < 4; ++in)
                    mma_tf32(acc[im][in], af[im], bf[in]);
        }
    }

#pragma unroll
    for (int im = 0; im < 4; ++im) {
        const int r0 = rowBase + wm * 64 + im * 16 + g;
#pragma unroll
        for (int in = 0; in < 4; ++in) {
            const int c0 = nb + wn * 32 + in * 8 + t4 * 2;
#pragma unroll
            for (int e = 0; e < 4; ++e) {
                const int row = r0 + ((e & 2) ? 8 : 0);
                const int col = c0 + (e & 1);
                if (col < NV)
                    C[(size_t)row * NV + col] = acc[im][in][e] + bias[col];
            }
        }
    }
}

// ---------------------------------------------------------------------------
// Fused pipelined RNN scan — 64 CTAs x 384 thr, crossbar-optimized.
//   Work unit = (matrix m in {Wh0,Wx1,Wh1}) x (4-col group g) x (K-half kh):
//   12 units = 12 warps. Each LDS.128 of h feeds 4 cols x 4 batches (FFMA2).
//   Epoch e: layer0: h0_e = tanh(XW0[:,e,:] + h0_{e-1}@Wh0)
//            layer1: h1_{e-1} = tanh(h0_{e-1}@Wx1 + h1_{e-2}@Wh1 + b1)
//   Reduce: 3-round f32x2 butterfly -> lanes 0..3 -> smem partials ->
//   64-thread parallel finale (tanh + stores).
//   Sync: one poller/CTA (ld.acquire) -> syncthreads; writes -> syncthreads
//   -> tid0 red.release. Depth-2 rings safe (joint barrier, reads precede
//   arrivals, so no CTA overwrites a slot others still read).
// ---------------------------------------------------------------------------
__global__ __launch_bounds__(384, 1)
void scan_fused(const float* __restrict__ XW0, const float* __restrict__ Wh0,
                const float* __restrict__ Wx1, const float* __restrict__ Wh1,
                const float* __restrict__ b1,  float* __restrict__ H1) {
    __shared__ float4 hT[1024];        // [0,512)=h0_{e-1}, [512,1024)=h1_{e-2}
    __shared__ float4 sred[12][4][4];  // [unit][laneset][col] = {b0..b3}

    const int tid  = threadIdx.x;
    const int lane = tid & 31;
    const int warp = tid >> 5;         // 0..11 == unit id
    const int blk  = blockIdx.x;       // 0..63

    // unit decomposition
    const int m  = warp >> 2;          // 0=Wh0, 1=Wx1, 2=Wh1
    const int g  = (warp >> 1) & 1;    // column group (4 cols)
    const int kh = warp & 1;           // K half (256)
    const int jb = blk * 8 + g * 4;    // first column of this unit

    // ---- preload 4 weight columns for this unit, packed (w,w) f32x2 ----
    const float* W = (m == 0) ? Wh0 : (m == 1) ? Wx1 : Wh1;
    unsigned long long wp[4][8];
#pragma unroll
    for (int i = 0; i < 8; ++i) {
        const size_t krow = (size_t)(kh * 256 + lane + 32 * i) * NL + jb;
#pragma unroll
        for (int c = 0; c < 4; ++c)
            wp[c][i] = fpack2(W[krow + c]);
    }

    // finale-thread constants (tid < 64): layer=tid>>5, col=(tid>>2)&7, b=tid&3
    const int f_c8 = (tid >> 2) & 7;
    const int f_b  = tid & 3;
    const int f_jw = blk * 8 + f_c8;
    const float bias1 = (tid >= 32 && tid < 64) ? b1[f_jw] : 0.f;

    // h read offset for this unit's K slice (Wh1 reads hT1 at +512)
    const int hoff = (m == 2 ? 512 : 0) + kh * 256 + lane;

    unsigned* const barp = &g_bar;

    for (int e = 0; e <= NT; ++e) {
        // prefetch XW0 for this epoch (independent of barrier/h)
        float xw = 0.f;
        if (tid < 32 && e < NT)
            xw = __ldg(&XW0[((size_t)f_b * NT + e) * NL + f_jw]);

        // ---- wait: single poller per CTA ----
        if (tid == 0 && e > 0) {
            const unsigned tgt = 64u * (unsigned)e;
            unsigned v;
            do {
                asm volatile("ld.acquire.gpu.global.u32 %0, [%1];"
                             : "=r"(v) : "l"(barp) : "memory");
            } while (v < tgt);
        }
        __syncthreads();

        // ---- stage h states (L2-coherent): h0 slot (e+1)&1, h1 slot e&1 ----
        {
            const float4* s0 = &g_h0[(e + 1) & 1][0];
            const float4* s1 = &g_h1[e & 1][0];
            for (int i = tid; i < 1024; i += 384)
                hT[i] = (i < 512) ? __ldcg(s0 + i) : __ldcg(s1 + (i - 512));
        }
        __syncthreads();

        // ---- unit matvec: 8 LDS.128, each feeding 16 FMA (8 FFMA2) ----
        unsigned long long a01[4] = {0ull, 0ull, 0ull, 0ull};
        unsigned long long a23[4] = {0ull, 0ull, 0ull, 0ull};
#pragma unroll
        for (int i = 0; i < 8; ++i) {
            const ulonglong2 hv = *(const ulonglong2*)&hT[hoff + 32 * i];
#pragma unroll
            for (int c = 0; c < 4; ++c) {
                ffma2(a01[c], hv.x, wp[c][i]);
                ffma2(a23[c], hv.y, wp[c][i]);
            }
        }

        // ---- 3-round butterfly to lanes 0..3 ----
#pragma unroll
        for (int off = 16; off >= 4; off >>= 1) {
#pragma unroll
            for (int c = 0; c < 4; ++c) {
                fadd2(a01[c], __shfl_down_sync(0xffffffffu, a01[c], off));
                fadd2(a23[c], __shfl_down_sync(0xffffffffu, a23[c], off));
            }
        }
        if (lane < 4) {
#pragma unroll
            for (int c = 0; c < 4; ++c) {
                float2 lo = *(const float2*)&a01[c];
                float2 hi = *(const float2*)&a23[c];
                sred[warp][lane][c] = make_float4(lo.x, lo.y, hi.x, hi.y);
            }
        }
        __syncthreads();

        // ---- parallel finale: 64 threads (32 layer0 + 32 layer1) ----
        if (tid < 64) {
            const float* sf = (const float*)sred;
            const int gg = f_c8 >> 2, cc = f_c8 & 3;
            if (tid < 32) {                       // layer0: h0_e
                if (e < NT) {
                    float s = xw;
                    const int u0 = gg * 2;        // m=0 units
#pragma unroll
                    for (int u = u0; u <= u0 + 1; ++u)
#pragma unroll
                        for (int ls = 0; ls < 4; ++ls)
                            s += sf[u * 64 + ls * 16 + cc * 4 + f_b];
                    const float hn = tanhf(s);
                    __stcg(&((float*)&g_h0[e & 1][f_jw])[f_b], hn);
                }
            } else {                              // layer1: h1_{e-1}
                if (e >= 1) {
                    float s = bias1;
#pragma unroll
                    for (int mm = 1; mm <= 2; ++mm) {
                        const int u0 = mm * 4 + gg * 2;
#pragma unroll
                        for (int u = u0; u <= u0 + 1; ++u)
#pragma unroll
                            for (int ls = 0; ls < 4; ++ls)
                                s += sf[u * 64 + ls * 16 + cc * 4 + f_b];
                    }
                    const float hn = tanhf(s);
                    __stcg(&((float*)&g_h1[(e + 1) & 1][f_jw])[f_b], hn);
                    H1[((size_t)f_b * NT + (e - 1)) * NL + f_jw] =
                        __uint_as_float(f2tf32(hn));   // pre-rounded for GEMM
                }
            }
        }

        if (e < NT) {
            __syncthreads();   // CTA-wide HB edge: writes -> tid0's release
            if (tid == 0)
                asm volatile("red.release.gpu.global.add.u32 [%0], %1;"
                             :: "l"(barp), "r"(1u) : "memory");
        }
    }
}

// ---------------------------------------------------------------------------
// Launch
// ---------------------------------------------------------------------------
extern "C" void kernel_launch(void* const* d_in, const int* in_sizes, int n_in,
                              void* d_out, int out_size) {
    const int*   x     = (const int*)  d_in[0];
    const float* embed = (const float*)d_in[1];
    const float* Wx0   = (const float*)d_in[2];
    const float* Wh0   = (const float*)d_in[3];
    const float* b0    = (const float*)d_in[4];
    const float* Wx1   = (const float*)d_in[5];
    const float* Wh1   = (const float*)d_in[6];
    const float* b1    = (const float*)d_in[7];
    const float* Wu    = (const float*)d_in[8];
    const float* bu    = (const float*)d_in[9];
    float* out = (float*)d_out;

    void *pA = nullptr, *pB = nullptr;
    cudaGetSymbolAddress(&pA, g_bufA);
    cudaGetSymbolAddress(&pB, g_bufB);
    float* bufA = (float*)pA;
    float* bufB = (float*)pB;

    cudaFuncSetAttribute(gemm_tf32,
                         cudaFuncAttributeMaxDynamicSharedMemorySize,
                         GEMM_SMEM);
    cudaFuncSetAttribute(gemm_unembed,
                         cudaFuncAttributeMaxDynamicSharedMemorySize,
                         UGEMM_SMEM);

    init_kernel<<<1, 256>>>();
    wu_prep<<<dim3((NVP + 255) / 256, NL), 256>>>(Wu);
    const dim3 gSmall(NL / BN, NR / BM);
    gemm_tf32<<<gSmall, GT, GEMM_SMEM>>>(embed, x, Wx0, b0, bufA, NL);
    scan_fused<<<64, 384>>>(bufA, Wh0, Wx1, Wh1, b1, bufB);
    const dim3 gBig(NVP / UBN, NR / UBM);
    gemm_unembed<<<gBig, 256, UGEMM_SMEM>>>(bufB, bu, out);
}

// round 9
// speedup vs baseline: 1.0749x; 1.0749x over previous
#include <cuda_runtime.h>
#include <cuda_bf16.h>
#include <math.h>
#include <stdint.h>

// ---------------------------------------------------------------------------
// Problem constants
// ---------------------------------------------------------------------------
#define NB   4        // batch
#define NT   1024     // time steps
#define NL   512      // latent / emb
#define NV   50257    // vocab
#define NR   (NB*NT)  // 4096 rows
#define NVP  50304    // padded vocab pitch (= 393*128, 16B-aligned rows)

// small GEMM tiling (register-staged)
#define BM   256
#define BN   128
#define BK   16
#define GT   512
#define GEMM_SMEM ((2*BM*20 + 2*BK*136)*4)

// big GEMM tiling (cp.async pipelined)
#define UBM 128
#define UBN 128
#define UBK 16
#define UST 4
#define UAS (UBM*20)
#define UBS (UBK*132)
#define UGEMM_SMEM (UST*(UAS+UBS)*4)

// ---------------------------------------------------------------------------
// Scratch (device globals — no allocation allowed)
// ---------------------------------------------------------------------------
__device__ float g_bufA[NR * NL];     // XW0 (= embed[x]@Wx0 + b0)
__device__ float g_bufB[NR * NL];     // H1, stored tf32-rounded
__device__ float g_wu[NL * NVP];      // Wu, tf32-rounded + padded
__device__ float4 g_h0[2][NL];        // depth-2 ring, layer-0 h, [k]={b0..b3}
__device__ float4 g_h1[2][NL];        // depth-2 ring, layer-1 h
__device__ unsigned g_bar;            // single joint barrier counter

// ---------------------------------------------------------------------------
// Helpers
// ---------------------------------------------------------------------------
__device__ __forceinline__ unsigned f2tf32(float f) {
    unsigned u;
    asm("cvt.rna.tf32.f32 %0, %1;" : "=r"(u) : "f"(f));
    return u;
}

__device__ __forceinline__ void mma_tf32(float c[4], const unsigned a[4],
                                         const unsigned b[2]) {
    asm volatile(
        "mma.sync.aligned.m16n8k8.row.col.f32.tf32.tf32.f32 "
        "{%0,%1,%2,%3},{%4,%5,%6,%7},{%8,%9},{%0,%1,%2,%3};"
        : "+f"(c[0]), "+f"(c[1]), "+f"(c[2]), "+f"(c[3])
        : "r"(a[0]), "r"(a[1]), "r"(a[2]), "r"(a[3]), "r"(b[0]), "r"(b[1]));
}

__device__ __forceinline__ void cp16(uint32_t dst, const void* src) {
    asm volatile("cp.async.cg.shared.global [%0], [%1], 16;\n"
                 :: "r"(dst), "l"(src));
}

// ---------------------------------------------------------------------------
// init: reset barrier + zero both h rings
// ---------------------------------------------------------------------------
__global__ void init_kernel() {
    const int tid = threadIdx.x;
    if (tid == 0) g_bar = 0u;
    float4 z = make_float4(0.f, 0.f, 0.f, 0.f);
    for (int i = tid; i < 2 * NL; i += 256) {
        ((float4*)g_h0)[i] = z;
        ((float4*)g_h1)[i] = z;
    }
}

// ---------------------------------------------------------------------------
// Wu prep: g_wu[k][n] = tf32_rna(Wu[k][n]), zero-padded to pitch NVP
// ---------------------------------------------------------------------------
__global__ void wu_prep(const float* __restrict__ Wu) {
    const int n = blockIdx.x * 256 + threadIdx.x;
    const int k = blockIdx.y;
    if (n < NVP)
        g_wu[(size_t)k * NVP + n] =
            (n < NV) ? __uint_as_float(f2tf32(Wu[(size_t)k * NV + n])) : 0.f;
}

// ---------------------------------------------------------------------------
// Small GEMM: C = A(gathered) @ B + bias (in-loop tf32 cvt). XW0 only.
// ---------------------------------------------------------------------------
__global__ __launch_bounds__(GT, 1)
void gemm_tf32(const float* __restrict__ A, const int* __restrict__ gidx,
               const float* __restrict__ B, const float* __restrict__ bias,
               float* __restrict__ C, int N) {
    extern __shared__ float sm[];
    float* As = sm;
    float* Bs = sm + 2 * BM * 20;

    const int tid  = threadIdx.x;
    const int lane = tid & 31;
    const int warp = tid >> 5;
    const int wm = warp & 3;
    const int wn = warp >> 2;
    const int g  = lane >> 2;
    const int t4 = lane & 3;

    const int rowBase = blockIdx.y * BM;
    const int nb      = blockIdx.x * BN;

    float acc[4][4][4];
#pragma unroll
    for (int a = 0; a < 4; ++a)
#pragma unroll
        for (int b = 0; b < 4; ++b)
#pragma unroll
            for (int e = 0; e < 4; ++e) acc[a][b][e] = 0.f;

    const int rl0 = tid >> 2;
    const int rl1 = rl0 + 128;
    const int c4  = tid & 3;
    const float* arow0;
    const float* arow1;
    {
        const int r0 = rowBase + rl0;
        const int r1 = rowBase + rl1;
        arow0 = A + (size_t)(gidx ? gidx[r0] : r0) * NL;
        arow1 = A + (size_t)(gidx ? gidx[r1] : r1) * NL;
    }

    float4 pa0, pa1;
    float  pb[4];
    pa0 = *(const float4*)(arow0 + c4 * 4);
    pa1 = *(const float4*)(arow1 + c4 * 4);
#pragma unroll
    for (int i = 0; i < 4; ++i) {
        const int id  = tid + i * GT;
        const int kr  = id >> 7;
        const int col = id & 127;
        const int n   = nb + col;
        pb[i] = (n < N) ? B[(size_t)kr * N + n] : 0.f;
    }

    int w = 0;
    for (int kb = 0; kb < NL; kb += BK) {
        {
            float4 w0, w1;
            w0.x = __uint_as_float(f2tf32(pa0.x));
            w0.y = __uint_as_float(f2tf32(pa0.y));
            w0.z = __uint_as_float(f2tf32(pa0.z));
            w0.w = __uint_as_float(f2tf32(pa0.w));
            w1.x = __uint_as_float(f2tf32(pa1.x));
            w1.y = __uint_as_float(f2tf32(pa1.y));
            w1.z = __uint_as_float(f2tf32(pa1.z));
            w1.w = __uint_as_float(f2tf32(pa1.w));
            *(float4*)&As[w * (BM * 20) + rl0 * 20 + c4 * 4] = w0;
            *(float4*)&As[w * (BM * 20) + rl1 * 20 + c4 * 4] = w1;
#pragma unroll
            for (int i = 0; i < 4; ++i) {
                const int id  = tid + i * GT;
                const int kr  = id >> 7;
                const int col = id & 127;
                Bs[w * (BK * 136) + kr * 136 + col] =
                    __uint_as_float(f2tf32(pb[i]));
            }
        }
        __syncthreads();

        if (kb + BK < NL) {
            pa0 = *(const float4*)(arow0 + kb + BK + c4 * 4);
            pa1 = *(const float4*)(arow1 + kb + BK + c4 * 4);
#pragma unroll
            for (int i = 0; i < 4; ++i) {
                const int id  = tid + i * GT;
                const int kr  = id >> 7;
                const int col = id & 127;
                const int n   = nb + col;
                pb[i] = (n < N) ? B[(size_t)(kb + BK + kr) * N + n] : 0.f;
            }
        }

        const float* Aw = &As[w * (BM * 20)];
        const float* Bw = &Bs[w * (BK * 136)];
#pragma unroll
        for (int ks = 0; ks < BK; ks += 8) {
            unsigned af[4][4], bf[4][2];
#pragma unroll
            for (int im = 0; im < 4; ++im) {
                const int m0 = wm * 64 + im * 16;
                const float* a0 = Aw + (m0 + g) * 20 + ks + t4;
                const float* a1 = Aw + (m0 + g + 8) * 20 + ks + t4;
                af[im][0] = __float_as_uint(a0[0]);
                af[im][1] = __float_as_uint(a1[0]);
                af[im][2] = __float_as_uint(a0[4]);
                af[im][3] = __float_as_uint(a1[4]);
            }
#pragma unroll
            for (int in = 0; in < 4; ++in) {
                const int n0 = wn * 32 + in * 8;
                bf[in][0] = __float_as_uint(Bw[(ks + t4) * 136 + n0 + g]);
                bf[in][1] = __float_as_uint(Bw[(ks + t4 + 4) * 136 + n0 + g]);
            }
#pragma unroll
            for (int im = 0; im < 4; ++im)
#pragma unroll
                for (int in = 0; in < 4; ++in)
                    mma_tf32(acc[im][in], af[im], bf[in]);
        }
        w ^= 1;
    }

#pragma unroll
    for (int im = 0; im < 4; ++im) {
        const int r0 = rowBase + wm * 64 + im * 16 + g;
#pragma unroll
        for (int in = 0; in < 4; ++in) {
            const int c0 = nb + wn * 32 + in * 8 + t4 * 2;
#pragma unroll
            for (int e = 0; e < 4; ++e) {
                const int row = r0 + ((e & 2) ? 8 : 0);
                const int col = c0 + (e & 1);
                if (col < N)
                    C[(size_t)row * N + col] = acc[im][in][e] + bias[col];
            }
        }
    }
}

// ---------------------------------------------------------------------------
// Big unembed GEMM: out = H1(tf32 bits) @ g_wu + bu. 128x128x16, cp.async x4.
//   Grid: x = ROW tiles (fastest-varying) so all 32 row-tiles of a column
//   band are co-resident -> the band's B slice + all of A stay L2-hot.
//   DRAM B traffic drops 32x (3.2GB -> 200MB).
// ---------------------------------------------------------------------------
__global__ __launch_bounds__(256, 2)
void gemm_unembed(const float* __restrict__ A, const float* __restrict__ bias,
                  float* __restrict__ C) {
    extern __shared__ float sm[];
    const uint32_t smem_u32 = (uint32_t)__cvta_generic_to_shared(sm);

    const int tid  = threadIdx.x;
    const int lane = tid & 31;
    const int warp = tid >> 5;
    const int wm = warp & 1;
    const int wn = warp >> 1;
    const int g  = lane >> 2;
    const int t4 = lane & 3;

    const int rowBase = blockIdx.x * UBM;   // row tiles vary fastest
    const int nb      = blockIdx.y * UBN;   // column band

    float acc[4][4][4];
#pragma unroll
    for (int a = 0; a < 4; ++a)
#pragma unroll
        for (int b = 0; b < 4; ++b)
#pragma unroll
            for (int e = 0; e < 4; ++e) acc[a][b][e] = 0.f;

    const int arow = tid >> 2;
    const int ac4  = tid & 3;
    const float* aptr0 = A + (size_t)(rowBase + arow) * NL + ac4 * 4;
    const float* aptr1 = A + (size_t)(rowBase + arow + 64) * NL + ac4 * 4;
    const int bkr0 = tid >> 5;
    const int bc0  = tid & 31;
    const float* bptr0 = g_wu + (size_t)bkr0 * NVP + nb + bc0 * 4;
    const float* bptr1 = g_wu + (size_t)(bkr0 + 8) * NVP + nb + bc0 * 4;

    const uint32_t adst0 = smem_u32 + (arow * 20 + ac4 * 4) * 4;
    const uint32_t adst1 = smem_u32 + ((arow + 64) * 20 + ac4 * 4) * 4;
    const uint32_t bdst0 = smem_u32 + (UST * UAS + bkr0 * 132 + bc0 * 4) * 4;
    const uint32_t bdst1 = smem_u32 + (UST * UAS + (bkr0 + 8) * 132 + bc0 * 4) * 4;

    const int NKT = NL / UBK;

#pragma unroll
    for (int s = 0; s < UST - 1; ++s) {
        const int kb = s * UBK;
        cp16(adst0 + s * UAS * 4, aptr0 + kb);
        cp16(adst1 + s * UAS * 4, aptr1 + kb);
        cp16(bdst0 + s * UBS * 4, bptr0 + (size_t)kb * NVP);
        cp16(bdst1 + s * UBS * 4, bptr1 + (size_t)kb * NVP);
        asm volatile("cp.async.commit_group;\n" ::);
    }

    for (int kt = 0; kt < NKT; ++kt) {
        asm volatile("cp.async.wait_group 2;\n" ::);
        __syncthreads();

        if (kt + UST - 1 < NKT) {
            const int s  = (kt + UST - 1) & (UST - 1);
            const int kb = (kt + UST - 1) * UBK;
            cp16(adst0 + s * UAS * 4, aptr0 + kb);
            cp16(adst1 + s * UAS * 4, aptr1 + kb);
            cp16(bdst0 + s * UBS * 4, bptr0 + (size_t)kb * NVP);
            cp16(bdst1 + s * UBS * 4, bptr1 + (size_t)kb * NVP);
        }
        asm volatile("cp.async.commit_group;\n" ::);

        const float* Aw = sm + (kt & (UST - 1)) * UAS;
        const float* Bw = sm + UST * UAS + (kt & (UST - 1)) * UBS;
#pragma unroll
        for (int ks = 0; ks < UBK; ks += 8) {
            unsigned af[4][4], bf[4][2];
#pragma unroll
            for (int im = 0; im < 4; ++im) {
                const int m0 = wm * 64 + im * 16;
                const float* a0 = Aw + (m0 + g) * 20 + ks + t4;
                const float* a1 = Aw + (m0 + g + 8) * 20 + ks + t4;
                af[im][0] = __float_as_uint(a0[0]);
                af[im][1] = __float_as_uint(a1[0]);
                af[im][2] = __float_as_uint(a0[4]);
                af[im][3] = __float_as_uint(a1[4]);
            }
#pragma unroll
            for (int in = 0; in < 4; ++in) {
                const int n0 = wn * 32 + in * 8;
                bf[in][0] = __float_as_uint(Bw[(ks + t4) * 132 + n0 + g]);
                bf[in][1] = __float_as_uint(Bw[(ks + t4 + 4) * 132 + n0 + g]);
            }
#pragma unroll
            for (int im = 0; im < 4; ++im)
#pragma unroll
                for (int in = 0; in < 4; ++in)
                    mma_tf32(acc[im][in], af[im], bf[in]);
        }
    }

#pragma unroll
    for (int im = 0; im < 4; ++im) {
        const int r0 = rowBase + wm * 64 + im * 16 + g;
#pragma unroll
        for (int in = 0; in < 4; ++in) {
            const int c0 = nb + wn * 32 + in * 8 + t4 * 2;
#pragma unroll
            for (int e = 0; e < 4; ++e) {
                const int row = r0 + ((e & 2) ? 8 : 0);
                const int col = c0 + (e & 1);
                if (col < NV)
                    C[(size_t)row * NV + col] = acc[im][in][e] + bias[col];
            }
        }
    }
}

// ---------------------------------------------------------------------------
// Fused pipelined RNN scan — 64 CTAs, BOTH layers per CTA, 1 joint barrier.
//   (Exact R7 version — best measured; compute restructures proved neutral.)
// ---------------------------------------------------------------------------
__global__ __launch_bounds__(256, 1)
void scan_fused(const float* __restrict__ XW0, const float* __restrict__ Wh0,
                const float* __restrict__ Wx1, const float* __restrict__ Wh1,
                const float* __restrict__ b1,  float* __restrict__ H1) {
    __shared__ float4 hT0[512];       // h0_{e-1}
    __shared__ float4 hT1[512];       // h1_{e-2}
    __shared__ float4 sred0[8][4];    // layer-0 per-warp partials
    __shared__ float4 sred1[8][4];    // layer-1 per-warp partials

    const int tid  = threadIdx.x;
    const int lane = tid & 31;
    const int warp = tid >> 5;        // 0..7
    const int blk  = blockIdx.x;      // 0..63
    const int jw   = blk * 8 + warp;  // this warp's column (both layers)

    float w0[16], w1x[16], w1h[16];
#pragma unroll
    for (int i = 0; i < 16; ++i) {
        const size_t k = (size_t)(lane + 32 * i) * NL + jw;
        w0[i]  = Wh0[k];
        w1x[i] = Wx1[k];
        w1h[i] = Wh1[k];
    }
    const float bias1 = (lane >= 4 && lane < 8) ? b1[jw] : 0.f;

    unsigned* const barp = &g_bar;
    const int i0 = tid, i1 = tid + 256;

    for (int e = 0; e <= NT; ++e) {
        const bool do0 = (e < NT);
        const bool do1 = (e >= 1);

        float xw = 0.f;
        if (do0 && lane < 4)
            xw = __ldg(&XW0[((size_t)lane * NT + e) * NL + jw]);

        if (tid == 0 && e > 0) {
            const unsigned tgt = 64u * (unsigned)e;
            unsigned v;
            do {
                asm volatile("ld.acquire.gpu.global.u32 %0, [%1];"
                             : "=r"(v) : "l"(barp) : "memory");
            } while (v < tgt);
        }
        __syncthreads();

        hT0[i0] = __ldcg(&g_h0[(e + 1) & 1][i0]);
        hT0[i1] = __ldcg(&g_h0[(e + 1) & 1][i1]);
        if (do1) {
            hT1[i0] = __ldcg(&g_h1[e & 1][i0]);
            hT1[i1] = __ldcg(&g_h1[e & 1][i1]);
        }
        __syncthreads();

        float ax = 0.f, ay = 0.f, az = 0.f, aw = 0.f;
        float bx = 0.f, by = 0.f, bz = 0.f, bw = 0.f;
#pragma unroll
        for (int i = 0; i < 16; ++i) {
            const float4 hv = hT0[lane + 32 * i];
            const float wa = w0[i];
            const float wb = w1x[i];
            ax = fmaf(wa, hv.x, ax);
            ay = fmaf(wa, hv.y, ay);
            az = fmaf(wa, hv.z, az);
            aw = fmaf(wa, hv.w, aw);
            bx = fmaf(wb, hv.x, bx);
            by = fmaf(wb, hv.y, by);
            bz = fmaf(wb, hv.z, bz);
            bw = fmaf(wb, hv.w, bw);
        }
        if (do1) {
#pragma unroll
            for (int i = 0; i < 16; ++i) {
                const float4 hv = hT1[lane + 32 * i];
                const float wb = w1h[i];
                bx = fmaf(wb, hv.x, bx);
                by = fmaf(wb, hv.y, by);
                bz = fmaf(wb, hv.z, bz);
                bw = fmaf(wb, hv.w, bw);
            }
        }

#pragma unroll
        for (int off = 16; off >= 4; off >>= 1) {
            ax += __shfl_down_sync(0xffffffffu, ax, off);
            ay += __shfl_down_sync(0xffffffffu, ay, off);
            az += __shfl_down_sync(0xffffffffu, az, off);
            aw += __shfl_down_sync(0xffffffffu, aw, off);
            bx += __shfl_down_sync(0xffffffffu, bx, off);
            by += __shfl_down_sync(0xffffffffu, by, off);
            bz += __shfl_down_sync(0xffffffffu, bz, off);
            bw += __shfl_down_sync(0xffffffffu, bw, off);
        }
        if (lane < 4) {
            sred0[warp][lane] = make_float4(ax, ay, az, aw);
            sred1[warp][lane] = make_float4(bx, by, bz, bw);
        }
        __syncwarp();

        if (do0 && lane < 4) {
            const float* p = (const float*)&sred0[warp][0];
            const float s = p[lane] + p[4 + lane] + p[8 + lane] + p[12 + lane];
            const float hn = tanhf(s + xw);
            __stcg(&((float*)&g_h0[e & 1][jw])[lane], hn);   // h0_e
        }
        if (do1 && lane >= 4 && lane < 8) {
            const int b = lane - 4;
            const float* p = (const float*)&sred1[warp][0];
            const float s = p[b] + p[4 + b] + p[8 + b] + p[12 + b];
            const float hn = tanhf(s + bias1);
            __stcg(&((float*)&g_h1[(e + 1) & 1][jw])[b], hn); // h1_{e-1}
            H1[((size_t)b * NT + (e - 1)) * NL + jw] =
                __uint_as_float(f2tf32(hn));   // pre-rounded for GEMM
        }

        if (e < NT) {
            __syncthreads();   // CTA-wide HB edge: writes -> tid0's release
            if (tid == 0)
                asm volatile("red.release.gpu.global.add.u32 [%0], %1;"
                             :: "l"(barp), "r"(1u) : "memory");
        }
    }
}

// ---------------------------------------------------------------------------
// Launch
// ---------------------------------------------------------------------------
extern "C" void kernel_launch(void* const* d_in, const int* in_sizes, int n_in,
                              void* d_out, int out_size) {
    const int*   x     = (const int*)  d_in[0];
    const float* embed = (const float*)d_in[1];
    const float* Wx0   = (const float*)d_in[2];
    const float* Wh0   = (const float*)d_in[3];
    const float* b0    = (const float*)d_in[4];
    const float* Wx1   = (const float*)d_in[5];
    const float* Wh1   = (const float*)d_in[6];
    const float* b1    = (const float*)d_in[7];
    const float* Wu    = (const float*)d_in[8];
    const float* bu    = (const float*)d_in[9];
    float* out = (float*)d_out;

    void *pA = nullptr, *pB = nullptr;
    cudaGetSymbolAddress(&pA, g_bufA);
    cudaGetSymbolAddress(&pB, g_bufB);
    float* bufA = (float*)pA;
    float* bufB = (float*)pB;

    cudaFuncSetAttribute(gemm_tf32,
                         cudaFuncAttributeMaxDynamicSharedMemorySize,
                         GEMM_SMEM);
    cudaFuncSetAttribute(gemm_unembed,
                         cudaFuncAttributeMaxDynamicSharedMemorySize,
                         UGEMM_SMEM);

    init_kernel<<<1, 256>>>();
    wu_prep<<<dim3((NVP + 255) / 256, NL), 256>>>(Wu);
    const dim3 gSmall(NL / BN, NR / BM);
    gemm_tf32<<<gSmall, GT, GEMM_SMEM>>>(embed, x, Wx0, b0, bufA, NL);
    scan_fused<<<64, 256>>>(bufA, Wh0, Wx1, Wh1, b1, bufB);
    // unembed: x = row tiles (fastest) for L2 reuse of the B column band
    const dim3 gBig(NR / UBM, NVP / UBN);   // (32, 393)
    gemm_unembed<<<gBig, 256, UGEMM_SMEM>>>(bufB, bu, out);
}

// round 10
// speedup vs baseline: 1.3308x; 1.2380x over previous
#include <cuda_runtime.h>
#include <cuda_bf16.h>
#include <math.h>
#include <stdint.h>

// ---------------------------------------------------------------------------
// Problem constants
// ---------------------------------------------------------------------------
#define NB   4        // batch
#define NT   1024     // time steps
#define NL   512      // latent / emb
#define NV   50257    // vocab
#define NR   (NB*NT)  // 4096 rows
#define NVP  50304    // padded vocab pitch (= 393*128, 16B-aligned rows)
#define NCT  393      // column tiles in unembed

// small GEMM tiling (register-staged)
#define BM   256
#define BN   128
#define BK   16
#define GT   512
#define GEMM_SMEM ((2*BM*20 + 2*BK*136)*4)

// big GEMM tiling (cp.async pipelined)
#define UBM 128
#define UBN 128
#define UBK 16
#define UST 4
#define UAS (UBM*20)
#define UBS (UBK*132)
#define FUSED_SMEM (UST*(UAS+UBS)*4)   // 74752 bytes (covers scan's 17.4KB too)

// ---------------------------------------------------------------------------
// Scratch (device globals — no allocation allowed)
// ---------------------------------------------------------------------------
__device__ float g_bufA[NR * NL];     // XW0 (= embed[x]@Wx0 + b0)
__device__ float g_bufB[NR * NL];     // H1, stored tf32-rounded
__device__ float g_wu[NL * NVP];      // Wu, tf32-rounded + padded
__device__ float4 g_h0[2][NL];        // depth-2 ring, layer-0 h, [k]={b0..b3}
__device__ float4 g_h1[2][NL];        // depth-2 ring, layer-1 h
__device__ unsigned g_bar;            // joint barrier / progress counter

// ---------------------------------------------------------------------------
// Helpers
// ---------------------------------------------------------------------------
__device__ __forceinline__ unsigned f2tf32(float f) {
    unsigned u;
    asm("cvt.rna.tf32.f32 %0, %1;" : "=r"(u) : "f"(f));
    return u;
}

__device__ __forceinline__ void mma_tf32(float c[4], const unsigned a[4],
                                         const unsigned b[2]) {
    asm volatile(
        "mma.sync.aligned.m16n8k8.row.col.f32.tf32.tf32.f32 "
        "{%0,%1,%2,%3},{%4,%5,%6,%7},{%8,%9},{%0,%1,%2,%3};"
        : "+f"(c[0]), "+f"(c[1]), "+f"(c[2]), "+f"(c[3])
        : "r"(a[0]), "r"(a[1]), "r"(a[2]), "r"(a[3]), "r"(b[0]), "r"(b[1]));
}

__device__ __forceinline__ void cp16(uint32_t dst, const void* src) {
    asm volatile("cp.async.cg.shared.global [%0], [%1], 16;\n"
                 :: "r"(dst), "l"(src));
}

// ---------------------------------------------------------------------------
// init: reset barrier + zero both h rings
// ---------------------------------------------------------------------------
__global__ void init_kernel() {
    const int tid = threadIdx.x;
    if (tid == 0) g_bar = 0u;
    float4 z = make_float4(0.f, 0.f, 0.f, 0.f);
    for (int i = tid; i < 2 * NL; i += 256) {
        ((float4*)g_h0)[i] = z;
        ((float4*)g_h1)[i] = z;
    }
}

// ---------------------------------------------------------------------------
// Wu prep: g_wu[k][n] = tf32_rna(Wu[k][n]), zero-padded to pitch NVP
// ---------------------------------------------------------------------------
__global__ void wu_prep(const float* __restrict__ Wu) {
    const int n = blockIdx.x * 256 + threadIdx.x;
    const int k = blockIdx.y;
    if (n < NVP)
        g_wu[(size_t)k * NVP + n] =
            (n < NV) ? __uint_as_float(f2tf32(Wu[(size_t)k * NV + n])) : 0.f;
}

// ---------------------------------------------------------------------------
// Small GEMM: C = A(gathered) @ B + bias (in-loop tf32 cvt). XW0 only.
// ---------------------------------------------------------------------------
__global__ __launch_bounds__(GT, 1)
void gemm_tf32(const float* __restrict__ A, const int* __restrict__ gidx,
               const float* __restrict__ B, const float* __restrict__ bias,
               float* __restrict__ C, int N) {
    extern __shared__ float sm[];
    float* As = sm;
    float* Bs = sm + 2 * BM * 20;

    const int tid  = threadIdx.x;
    const int lane = tid & 31;
    const int warp = tid >> 5;
    const int wm = warp & 3;
    const int wn = warp >> 2;
    const int g  = lane >> 2;
    const int t4 = lane & 3;

    const int rowBase = blockIdx.y * BM;
    const int nb      = blockIdx.x * BN;

    float acc[4][4][4];
#pragma unroll
    for (int a = 0; a < 4; ++a)
#pragma unroll
        for (int b = 0; b < 4; ++b)
#pragma unroll
            for (int e = 0; e < 4; ++e) acc[a][b][e] = 0.f;

    const int rl0 = tid >> 2;
    const int rl1 = rl0 + 128;
    const int c4  = tid & 3;
    const float* arow0;
    const float* arow1;
    {
        const int r0 = rowBase + rl0;
        const int r1 = rowBase + rl1;
        arow0 = A + (size_t)(gidx ? gidx[r0] : r0) * NL;
        arow1 = A + (size_t)(gidx ? gidx[r1] : r1) * NL;
    }

    float4 pa0, pa1;
    float  pb[4];
    pa0 = *(const float4*)(arow0 + c4 * 4);
    pa1 = *(const float4*)(arow1 + c4 * 4);
#pragma unroll
    for (int i = 0; i < 4; ++i) {
        const int id  = tid + i * GT;
        const int kr  = id >> 7;
        const int col = id & 127;
        const int n   = nb + col;
        pb[i] = (n < N) ? B[(size_t)kr * N + n] : 0.f;
    }

    int w = 0;
    for (int kb = 0; kb < NL; kb += BK) {
        {
            float4 w0, w1;
            w0.x = __uint_as_float(f2tf32(pa0.x));
            w0.y = __uint_as_float(f2tf32(pa0.y));
            w0.z = __uint_as_float(f2tf32(pa0.z));
            w0.w = __uint_as_float(f2tf32(pa0.w));
            w1.x = __uint_as_float(f2tf32(pa1.x));
            w1.y = __uint_as_float(f2tf32(pa1.y));
            w1.z = __uint_as_float(f2tf32(pa1.z));
            w1.w = __uint_as_float(f2tf32(pa1.w));
            *(float4*)&As[w * (BM * 20) + rl0 * 20 + c4 * 4] = w0;
            *(float4*)&As[w * (BM * 20) + rl1 * 20 + c4 * 4] = w1;
#pragma unroll
            for (int i = 0; i < 4; ++i) {
                const int id  = tid + i * GT;
                const int kr  = id >> 7;
                const int col = id & 127;
                Bs[w * (BK * 136) + kr * 136 + col] =
                    __uint_as_float(f2tf32(pb[i]));
            }
        }
        __syncthreads();

        if (kb + BK < NL) {
            pa0 = *(const float4*)(arow0 + kb + BK + c4 * 4);
            pa1 = *(const float4*)(arow1 + kb + BK + c4 * 4);
#pragma unroll
            for (int i = 0; i < 4; ++i) {
                const int id  = tid + i * GT;
                const int kr  = id >> 7;
                const int col = id & 127;
                const int n   = nb + col;
                pb[i] = (n < N) ? B[(size_t)(kb + BK + kr) * N + n] : 0.f;
            }
        }

        const float* Aw = &As[w * (BM * 20)];
        const float* Bw = &Bs[w * (BK * 136)];
#pragma unroll
        for (int ks = 0; ks < BK; ks += 8) {
            unsigned af[4][4], bf[4][2];
#pragma unroll
            for (int im = 0; im < 4; ++im) {
                const int m0 = wm * 64 + im * 16;
                const float* a0 = Aw + (m0 + g) * 20 + ks + t4;
                const float* a1 = Aw + (m0 + g + 8) * 20 + ks + t4;
                af[im][0] = __float_as_uint(a0[0]);
                af[im][1] = __float_as_uint(a1[0]);
                af[im][2] = __float_as_uint(a0[4]);
                af[im][3] = __float_as_uint(a1[4]);
            }
#pragma unroll
            for (int in = 0; in < 4; ++in) {
                const int n0 = wn * 32 + in * 8;
                bf[in][0] = __float_as_uint(Bw[(ks + t4) * 136 + n0 + g]);
                bf[in][1] = __float_as_uint(Bw[(ks + t4 + 4) * 136 + n0 + g]);
            }
#pragma unroll
            for (int im = 0; im < 4; ++im)
#pragma unroll
                for (int in = 0; in < 4; ++in)
                    mma_tf32(acc[im][in], af[im], bf[in]);
        }
        w ^= 1;
    }

#pragma unroll
    for (int im = 0; im < 4; ++im) {
        const int r0 = rowBase + wm * 64 + im * 16 + g;
#pragma unroll
        for (int in = 0; in < 4; ++in) {
            const int c0 = nb + wn * 32 + in * 8 + t4 * 2;
#pragma unroll
            for (int e = 0; e < 4; ++e) {
                const int row = r0 + ((e & 2) ? 8 : 0);
                const int col = c0 + (e & 1);
                if (col < N)
                    C[(size_t)row * N + col] = acc[im][in][e] + bias[col];
            }
        }
    }
}

// ---------------------------------------------------------------------------
// FUSED scan + unembed.
//   Blocks 0..63: R7 scan (both RNN layers, joint barrier), PLUS a release
//   at epoch NT so H1[t=1023] is signalled (counter reaches 64*(NT+1)).
//   Blocks >=64: unembed workers. uid = bid-64; group jj = uid/1572 (t-block),
//   batch bb = (uid%1572)/393, col x = uid%393. Tile rows = bb*1024+128*jj..+128.
//   Worker spins (nanosleep backoff) until counter >= 64*(128*(jj+1)+1)
//   [H1[t] visible when counter >= 64*(t+2)], then runs the cp.async GEMM tile.
//   Scan CTAs are wave-1 residents (bids 0..63, 2 CTAs/SM) => no deadlock;
//   every worker's target is eventually reached.
// ---------------------------------------------------------------------------
__global__ __launch_bounds__(256, 2)
void fused_scan_unembed(const float* __restrict__ XW0,
                        const float* __restrict__ Wh0,
                        const float* __restrict__ Wx1,
                        const float* __restrict__ Wh1,
                        const float* __restrict__ b1,
                        float* __restrict__ H1,
                        const float* __restrict__ bias,
                        float* __restrict__ C) {
    extern __shared__ float sm[];
    unsigned* const barp = &g_bar;
    const int tid  = threadIdx.x;

    if (blockIdx.x < 64) {
        // ===================== SCAN (R7 body) =====================
        float4* hT0 = (float4*)sm;            // 512
        float4* hT1 = hT0 + 512;              // 512
        float4* sred0 = hT1 + 512;            // [8][4]
        float4* sred1 = sred0 + 32;           // [8][4]

        const int lane = tid & 31;
        const int warp = tid >> 5;
        const int blk  = blockIdx.x;
        const int jw   = blk * 8 + warp;

        float w0[16], w1x[16], w1h[16];
#pragma unroll
        for (int i = 0; i < 16; ++i) {
            const size_t k = (size_t)(lane + 32 * i) * NL + jw;
            w0[i]  = Wh0[k];
            w1x[i] = Wx1[k];
            w1h[i] = Wh1[k];
        }
        const float bias1 = (lane >= 4 && lane < 8) ? b1[jw] : 0.f;
        const int i0 = tid, i1 = tid + 256;

        for (int e = 0; e <= NT; ++e) {
            const bool do0 = (e < NT);
            const bool do1 = (e >= 1);

            float xw = 0.f;
            if (do0 && lane < 4)
                xw = __ldg(&XW0[((size_t)lane * NT + e) * NL + jw]);

            if (tid == 0 && e > 0) {
                const unsigned tgt = 64u * (unsigned)e;
                unsigned v;
                do {
                    asm volatile("ld.acquire.gpu.global.u32 %0, [%1];"
                                 : "=r"(v) : "l"(barp) : "memory");
                } while (v < tgt);
            }
            __syncthreads();

            hT0[i0] = __ldcg(&g_h0[(e + 1) & 1][i0]);
            hT0[i1] = __ldcg(&g_h0[(e + 1) & 1][i1]);
            if (do1) {
                hT1[i0] = __ldcg(&g_h1[e & 1][i0]);
                hT1[i1] = __ldcg(&g_h1[e & 1][i1]);
            }
            __syncthreads();

            float ax = 0.f, ay = 0.f, az = 0.f, aw = 0.f;
            float bx = 0.f, by = 0.f, bz = 0.f, bw = 0.f;
#pragma unroll
            for (int i = 0; i < 16; ++i) {
                const float4 hv = hT0[lane + 32 * i];
                const float wa = w0[i];
                const float wb = w1x[i];
                ax = fmaf(wa, hv.x, ax);
                ay = fmaf(wa, hv.y, ay);
                az = fmaf(wa, hv.z, az);
                aw = fmaf(wa, hv.w, aw);
                bx = fmaf(wb, hv.x, bx);
                by = fmaf(wb, hv.y, by);
                bz = fmaf(wb, hv.z, bz);
                bw = fmaf(wb, hv.w, bw);
            }
            if (do1) {
#pragma unroll
                for (int i = 0; i < 16; ++i) {
                    const float4 hv = hT1[lane + 32 * i];
                    const float wb = w1h[i];
                    bx = fmaf(wb, hv.x, bx);
                    by = fmaf(wb, hv.y, by);
                    bz = fmaf(wb, hv.z, bz);
                    bw = fmaf(wb, hv.w, bw);
                }
            }

#pragma unroll
            for (int off = 16; off >= 4; off >>= 1) {
                ax += __shfl_down_sync(0xffffffffu, ax, off);
                ay += __shfl_down_sync(0xffffffffu, ay, off);
                az += __shfl_down_sync(0xffffffffu, az, off);
                aw += __shfl_down_sync(0xffffffffu, aw, off);
                bx += __shfl_down_sync(0xffffffffu, bx, off);
                by += __shfl_down_sync(0xffffffffu, by, off);
                bz += __shfl_down_sync(0xffffffffu, bz, off);
                bw += __shfl_down_sync(0xffffffffu, bw, off);
            }
            if (lane < 4) {
                sred0[warp * 4 + lane] = make_float4(ax, ay, az, aw);
                sred1[warp * 4 + lane] = make_float4(bx, by, bz, bw);
            }
            __syncwarp();

            if (do0 && lane < 4) {
                const float* p = (const float*)&sred0[warp * 4];
                const float s = p[lane] + p[4 + lane] + p[8 + lane] + p[12 + lane];
                const float hn = tanhf(s + xw);
                __stcg(&((float*)&g_h0[e & 1][jw])[lane], hn);
            }
            if (do1 && lane >= 4 && lane < 8) {
                const int b = lane - 4;
                const float* p = (const float*)&sred1[warp * 4];
                const float s = p[b] + p[4 + b] + p[8 + b] + p[12 + b];
                const float hn = tanhf(s + bias1);
                __stcg(&((float*)&g_h1[(e + 1) & 1][jw])[b], hn);
                H1[((size_t)b * NT + (e - 1)) * NL + jw] =
                    __uint_as_float(f2tf32(hn));
            }

            // release EVERY epoch (incl. e == NT, signalling H1[t=1023])
            __syncthreads();
            if (tid == 0)
                asm volatile("red.release.gpu.global.add.u32 [%0], %1;"
                             :: "l"(barp), "r"(1u) : "memory");
        }
        return;
    }

    // ===================== UNEMBED worker =====================
    {
        const int uid = (int)blockIdx.x - 64;
        const int jj  = uid / (4 * NCT);          // t-block 0..7
        const int rem = uid % (4 * NCT);
        const int bb  = rem / NCT;                // batch 0..3
        const int x   = rem % NCT;                // column tile 0..392
        const int rowBase = bb * 1024 + jj * 128;
        const int nb      = x * UBN;

        // wait until H1 rows [rowBase, rowBase+128) are published
        const unsigned tgt = 64u * (unsigned)(128 * (jj + 1) + 1);
        if (tid == 0) {
            unsigned v;
            for (;;) {
                asm volatile("ld.acquire.gpu.global.u32 %0, [%1];"
                             : "=r"(v) : "l"(barp) : "memory");
                if (v >= tgt) break;
                __nanosleep(256);
            }
        }
        __syncthreads();

        const float* A = H1;
        const uint32_t smem_u32 = (uint32_t)__cvta_generic_to_shared(sm);
        const int lane = tid & 31;
        const int warp = tid >> 5;
        const int wm = warp & 1;
        const int wn = warp >> 1;
        const int g  = lane >> 2;
        const int t4 = lane & 3;

        float acc[4][4][4];
#pragma unroll
        for (int a = 0; a < 4; ++a)
#pragma unroll
            for (int b = 0; b < 4; ++b)
#pragma unroll
                for (int e = 0; e < 4; ++e) acc[a][b][e] = 0.f;

        const int arow = tid >> 2;
        const int ac4  = tid & 3;
        const float* aptr0 = A + (size_t)(rowBase + arow) * NL + ac4 * 4;
        const float* aptr1 = A + (size_t)(rowBase + arow + 64) * NL + ac4 * 4;
        const int bkr0 = tid >> 5;
        const int bc0  = tid & 31;
        const float* bptr0 = g_wu + (size_t)bkr0 * NVP + nb + bc0 * 4;
        const float* bptr1 = g_wu + (size_t)(bkr0 + 8) * NVP + nb + bc0 * 4;

        const uint32_t adst0 = smem_u32 + (arow * 20 + ac4 * 4) * 4;
        const uint32_t adst1 = smem_u32 + ((arow + 64) * 20 + ac4 * 4) * 4;
        const uint32_t bdst0 = smem_u32 + (UST * UAS + bkr0 * 132 + bc0 * 4) * 4;
        const uint32_t bdst1 = smem_u32 + (UST * UAS + (bkr0 + 8) * 132 + bc0 * 4) * 4;

        const int NKT = NL / UBK;

#pragma unroll
        for (int s = 0; s < UST - 1; ++s) {
            const int kb = s * UBK;
            cp16(adst0 + s * UAS * 4, aptr0 + kb);
            cp16(adst1 + s * UAS * 4, aptr1 + kb);
            cp16(bdst0 + s * UBS * 4, bptr0 + (size_t)kb * NVP);
            cp16(bdst1 + s * UBS * 4, bptr1 + (size_t)kb * NVP);
            asm volatile("cp.async.commit_group;\n" ::);
        }

        for (int kt = 0; kt < NKT; ++kt) {
            asm volatile("cp.async.wait_group 2;\n" ::);
            __syncthreads();

            if (kt + UST - 1 < NKT) {
                const int s  = (kt + UST - 1) & (UST - 1);
                const int kb = (kt + UST - 1) * UBK;
                cp16(adst0 + s * UAS * 4, aptr0 + kb);
                cp16(adst1 + s * UAS * 4, aptr1 + kb);
                cp16(bdst0 + s * UBS * 4, bptr0 + (size_t)kb * NVP);
                cp16(bdst1 + s * UBS * 4, bptr1 + (size_t)kb * NVP);
            }
            asm volatile("cp.async.commit_group;\n" ::);

            const float* Aw = sm + (kt & (UST - 1)) * UAS;
            const float* Bw = sm + UST * UAS + (kt & (UST - 1)) * UBS;
#pragma unroll
            for (int ks = 0; ks < UBK; ks += 8) {
                unsigned af[4][4], bf[4][2];
#pragma unroll
                for (int im = 0; im < 4; ++im) {
                    const int m0 = wm * 64 + im * 16;
                    const float* a0 = Aw + (m0 + g) * 20 + ks + t4;
                    const float* a1 = Aw + (m0 + g + 8) * 20 + ks + t4;
                    af[im][0] = __float_as_uint(a0[0]);
                    af[im][1] = __float_as_uint(a1[0]);
                    af[im][2] = __float_as_uint(a0[4]);
                    af[im][3] = __float_as_uint(a1[4]);
                }
#pragma unroll
                for (int in = 0; in < 4; ++in) {
                    const int n0 = wn * 32 + in * 8;
                    bf[in][0] = __float_as_uint(Bw[(ks + t4) * 132 + n0 + g]);
                    bf[in][1] = __float_as_uint(Bw[(ks + t4 + 4) * 132 + n0 + g]);
                }
#pragma unroll
                for (int im = 0; im < 4; ++im)
#pragma unroll
                    for (int in = 0; in < 4; ++in)
                        mma_tf32(acc[im][in], af[im], bf[in]);
            }
        }

#pragma unroll
        for (int im = 0; im < 4; ++im) {
            const int r0 = rowBase + wm * 64 + im * 16 + g;
#pragma unroll
            for (int in = 0; in < 4; ++in) {
                const int c0 = nb + wn * 32 + in * 8 + t4 * 2;
#pragma unroll
                for (int e = 0; e < 4; ++e) {
                    const int row = r0 + ((e & 2) ? 8 : 0);
                    const int col = c0 + (e & 1);
                    if (col < NV)
                        C[(size_t)row * NV + col] = acc[im][in][e] + bias[col];
                }
            }
        }
    }
}

// ---------------------------------------------------------------------------
// Launch
// ---------------------------------------------------------------------------
extern "C" void kernel_launch(void* const* d_in, const int* in_sizes, int n_in,
                              void* d_out, int out_size) {
    const int*   x     = (const int*)  d_in[0];
    const float* embed = (const float*)d_in[1];
    const float* Wx0   = (const float*)d_in[2];
    const float* Wh0   = (const float*)d_in[3];
    const float* b0    = (const float*)d_in[4];
    const float* Wx1   = (const float*)d_in[5];
    const float* Wh1   = (const float*)d_in[6];
    const float* b1    = (const float*)d_in[7];
    const float* Wu    = (const float*)d_in[8];
    const float* bu    = (const float*)d_in[9];
    float* out = (float*)d_out;

    void *pA = nullptr, *pB = nullptr;
    cudaGetSymbolAddress(&pA, g_bufA);
    cudaGetSymbolAddress(&pB, g_bufB);
    float* bufA = (float*)pA;
    float* bufB = (float*)pB;

    cudaFuncSetAttribute(gemm_tf32,
                         cudaFuncAttributeMaxDynamicSharedMemorySize,
                         GEMM_SMEM);
    cudaFuncSetAttribute(fused_scan_unembed,
                         cudaFuncAttributeMaxDynamicSharedMemorySize,
                         FUSED_SMEM);

    init_kernel<<<1, 256>>>();
    wu_prep<<<dim3((NVP + 255) / 256, NL), 256>>>(Wu);
    const dim3 gSmall(NL / BN, NR / BM);
    gemm_tf32<<<gSmall, GT, GEMM_SMEM>>>(embed, x, Wx0, b0, bufA, NL);
    // fused: 64 scan CTAs + 12576 unembed workers, one launch
    const int nWorkers = 8 * 4 * NCT;   // 12576
    fused_scan_unembed<<<64 + nWorkers, 256, FUSED_SMEM>>>(
        bufA, Wh0, Wx1, Wh1, b1, bufB, bu, out);
}